// round 3
// baseline (speedup 1.0000x reference)
#include <cuda_runtime.h>
#include <cuda_fp16.h>
#include <cstdint>
#include <cstddef>

// ======================= problem dims (fixed) =======================
#define T_STEPS 25
#define BATCH   1024
#define IN_DIM  1024
#define HID_DIM 4096
#define OUT_DIM 64
#define M_ROWS  (T_STEPS * BATCH)   // 25600

#define LO_SCALE     1024.0f
#define LO_INV_SCALE (1.0f / 1024.0f)

// ======================= static device scratch =======================
__device__ __half g_A    [(size_t)M_ROWS * IN_DIM];     // fp16 input spikes (exact 0/1)
__device__ __half g_w1hi [(size_t)HID_DIM * IN_DIM];
__device__ __half g_w1lo [(size_t)HID_DIM * IN_DIM];    // (w - hi) * 1024, fp16-normal
__device__ __half g_w2hi [(size_t)OUT_DIM * HID_DIM];
__device__ __half g_w2lo [(size_t)OUT_DIM * HID_DIM];
__device__ float  g_cur1 [(size_t)M_ROWS * HID_DIM];    // layer-1 currents
__device__ __half g_spk1 [(size_t)M_ROWS * HID_DIM];    // layer-1 spikes (exact 0/1)
__device__ float  g_cur2 [(size_t)M_ROWS * OUT_DIM];    // layer-2 currents

// ======================= small helpers =======================
__device__ __forceinline__ void cp16(void* dst_smem, const void* src_gmem) {
    uint32_t d = (uint32_t)__cvta_generic_to_shared(dst_smem);
    asm volatile("cp.async.cg.shared.global [%0], [%1], 16;" :: "r"(d), "l"(src_gmem));
}
__device__ __forceinline__ void cp_commit() {
    asm volatile("cp.async.commit_group;");
}
__device__ __forceinline__ void cp_wait1() {
    asm volatile("cp.async.wait_group 1;");
}
__device__ __forceinline__ void cp_wait0() {
    asm volatile("cp.async.wait_group 0;");
}

// mma.sync m16n8k16, fp16 in / fp32 accum, row.col
__device__ __forceinline__ void mma16816(float* c, const uint32_t* a, uint32_t b0, uint32_t b1) {
    asm volatile(
        "mma.sync.aligned.m16n8k16.row.col.f32.f16.f16.f32 "
        "{%0,%1,%2,%3}, {%4,%5,%6,%7}, {%8,%9}, {%0,%1,%2,%3};"
        : "+f"(c[0]), "+f"(c[1]), "+f"(c[2]), "+f"(c[3])
        : "r"(a[0]), "r"(a[1]), "r"(a[2]), "r"(a[3]), "r"(b0), "r"(b1));
}

// ======================= prep kernels =======================
__global__ void k_cvt_spikes(const float* __restrict__ x, __half* __restrict__ y, int n) {
    for (int i = blockIdx.x * blockDim.x + threadIdx.x; i < n; i += gridDim.x * blockDim.x)
        y[i] = __float2half_rn(x[i]);   // 0.0 / 1.0 -> exact fp16
}

__global__ void k_split(const float* __restrict__ w, __half* __restrict__ hi,
                        __half* __restrict__ lo, int n) {
    for (int i = blockIdx.x * blockDim.x + threadIdx.x; i < n; i += gridDim.x * blockDim.x) {
        float v = w[i];
        __half h = __float2half_rn(v);
        hi[i] = h;
        // residual scaled into fp16-normal range; unscaled in GEMM epilogue
        lo[i] = __float2half_rn(__fmul_rn(__fsub_rn(v, __half2float(h)), LO_SCALE));
    }
}

// ======================= GEMM: C[M,N] = A[M,K] @ (Whi + Wlo/1024)[N,K]^T + bias ==========
// A fp16 row-major (K contiguous, exact 0/1), W fp16 row-major [N,K] == col-major B.
// Double-buffered cp.async pipeline. Separate fp32 accumulators for hi and lo planes;
// combined as acc_hi + acc_lo/1024 + bias in the epilogue (spike*w products are exact,
// so result carries only fp32 accumulation-order noise).
template <int BM, int BN, int BK, int WM, int WN>
__global__ void __launch_bounds__((BM / WM) * (BN / WN) * 32, 1)
gemm_hilo(const __half* __restrict__ A,
          const __half* __restrict__ Whi,
          const __half* __restrict__ Wlo,
          const float* __restrict__ bias,
          float* __restrict__ C,
          int M, int N, int K)
{
    constexpr int BKP     = BK + 8;                 // padded k-stride (halves)
    constexpr int NWARPS  = (BM / WM) * (BN / WN);
    constexpr int NTH     = NWARPS * 32;
    constexpr int MT      = WM / 16;                // m16 tiles per warp
    constexpr int NT      = WN / 8;                 // n8  tiles per warp
    constexpr int KCH     = BK / 8;                 // 16B chunks per row
    constexpr int ACH     = BM * KCH;
    constexpr int BCH     = BN * KCH;

    extern __shared__ __align__(16) unsigned char smem_raw[];
    __half* As = reinterpret_cast<__half*>(smem_raw);              // [2][BM][BKP]
    __half* Bs = As + 2 * BM * BKP;                                 // [2][2][BN][BKP]

    const int tid  = threadIdx.x;
    const int wid  = tid >> 5;
    const int lane = tid & 31;
    const int grp  = lane >> 2;       // 0..7
    const int q    = lane & 3;        // 0..3

    const int wm0 = (wid % (BM / WM)) * WM;
    const int wn0 = (wid / (BM / WM)) * WN;

    const int bm0 = blockIdx.y * BM;
    const int bn0 = blockIdx.x * BN;

    const int NK = K / BK;

    float acc_h[MT][NT][4];
    float acc_l[MT][NT][4];
#pragma unroll
    for (int i = 0; i < MT; i++)
#pragma unroll
        for (int j = 0; j < NT; j++)
#pragma unroll
            for (int e = 0; e < 4; e++) { acc_h[i][j][e] = 0.f; acc_l[i][j][e] = 0.f; }

    auto load_stage = [&](int stage, int kt) {
        const int k0 = kt * BK;
#pragma unroll
        for (int c = tid; c < ACH; c += NTH) {
            int row = c / KCH;
            int kc  = (c % KCH) * 8;
            cp16(&As[(stage * BM + row) * BKP + kc],
                 A + (size_t)(bm0 + row) * K + k0 + kc);
        }
#pragma unroll
        for (int c = tid; c < BCH; c += NTH) {
            int row = c / KCH;
            int kc  = (c % KCH) * 8;
            size_t g = (size_t)(bn0 + row) * K + k0 + kc;
            cp16(&Bs[((stage * 2 + 0) * BN + row) * BKP + kc], Whi + g);
            cp16(&Bs[((stage * 2 + 1) * BN + row) * BKP + kc], Wlo + g);
        }
    };

    load_stage(0, 0);
    cp_commit();

    for (int kt = 0; kt < NK; kt++) {
        const int buf = kt & 1;
        if (kt + 1 < NK) {
            load_stage(buf ^ 1, kt + 1);
            cp_commit();
            cp_wait1();
        } else {
            cp_wait0();
        }
        __syncthreads();

#pragma unroll
        for (int kk = 0; kk < BK / 16; kk++) {
            uint32_t afrag[MT][4];
#pragma unroll
            for (int i = 0; i < MT; i++) {
                const __half* ab = &As[(buf * BM + wm0 + i * 16) * BKP + kk * 16];
                afrag[i][0] = *(const uint32_t*)(ab + grp * BKP + q * 2);
                afrag[i][1] = *(const uint32_t*)(ab + (grp + 8) * BKP + q * 2);
                afrag[i][2] = *(const uint32_t*)(ab + grp * BKP + q * 2 + 8);
                afrag[i][3] = *(const uint32_t*)(ab + (grp + 8) * BKP + q * 2 + 8);
            }
#pragma unroll
            for (int j = 0; j < NT; j++) {
                const __half* bbh =
                    &Bs[((buf * 2 + 0) * BN + wn0 + j * 8 + grp) * BKP + kk * 16];
                uint32_t bh0 = *(const uint32_t*)(bbh + q * 2);
                uint32_t bh1 = *(const uint32_t*)(bbh + q * 2 + 8);
#pragma unroll
                for (int i = 0; i < MT; i++) mma16816(acc_h[i][j], afrag[i], bh0, bh1);

                const __half* bbl =
                    &Bs[((buf * 2 + 1) * BN + wn0 + j * 8 + grp) * BKP + kk * 16];
                uint32_t bl0 = *(const uint32_t*)(bbl + q * 2);
                uint32_t bl1 = *(const uint32_t*)(bbl + q * 2 + 8);
#pragma unroll
                for (int i = 0; i < MT; i++) mma16816(acc_l[i][j], afrag[i], bl0, bl1);
            }
        }
        __syncthreads();
    }

    // epilogue: C = acc_hi + acc_lo/1024 + bias
#pragma unroll
    for (int i = 0; i < MT; i++) {
#pragma unroll
        for (int j = 0; j < NT; j++) {
            int row0 = bm0 + wm0 + i * 16 + grp;
            int row1 = row0 + 8;
            int col  = bn0 + wn0 + j * 8 + q * 2;
            float bv0 = bias[col];
            float bv1 = bias[col + 1];
            float v00 = fmaf(acc_l[i][j][0], LO_INV_SCALE, acc_h[i][j][0]) + bv0;
            float v01 = fmaf(acc_l[i][j][1], LO_INV_SCALE, acc_h[i][j][1]) + bv1;
            float v10 = fmaf(acc_l[i][j][2], LO_INV_SCALE, acc_h[i][j][2]) + bv0;
            float v11 = fmaf(acc_l[i][j][3], LO_INV_SCALE, acc_h[i][j][3]) + bv1;
            *(float2*)&C[(size_t)row0 * N + col] = make_float2(v00, v01);
            *(float2*)&C[(size_t)row1 * N + col] = make_float2(v10, v11);
        }
    }
}

// ======================= LIF layer 1: currents -> spikes (fp16) =======================
// mem_t = 0.9*mem + cur_t - spk_{t-1};  spk_t = (mem_t - 1 > 0)
// Exact op order matches ((beta*mem)+cur)-spk via _rn intrinsics (no FMA contraction).
__global__ void lif1_kernel(const float* __restrict__ cur, __half* __restrict__ spk) {
    int idx = blockIdx.x * blockDim.x + threadIdx.x;
    if (idx >= BATCH * HID_DIM) return;
    const size_t base = (size_t)idx;              // = b*HID + h
    float mem = 0.f, sp = 0.f;
#pragma unroll
    for (int t = 0; t < T_STEPS; t++) {
        float c = cur[(size_t)t * BATCH * HID_DIM + base];
        mem = __fsub_rn(__fadd_rn(__fmul_rn(0.9f, mem), c), sp);
        sp  = (mem > 1.0f) ? 1.f : 0.f;
        spk[(size_t)t * BATCH * HID_DIM + base] = __float2half_rn(sp);
    }
}

// ======================= LIF layer 2: currents -> spike counts =======================
__global__ void lif2_kernel(const float* __restrict__ cur, float* __restrict__ out) {
    int idx = blockIdx.x * blockDim.x + threadIdx.x;
    if (idx >= BATCH * OUT_DIM) return;
    const size_t base = (size_t)idx;              // = b*OUT + o
    float mem = 0.f, sp = 0.f, cnt = 0.f;
#pragma unroll
    for (int t = 0; t < T_STEPS; t++) {
        float c = cur[(size_t)t * BATCH * OUT_DIM + base];
        mem = __fsub_rn(__fadd_rn(__fmul_rn(0.9f, mem), c), sp);
        sp  = (mem > 1.0f) ? 1.f : 0.f;
        cnt += sp;
    }
    out[base] = cnt;
}

// ======================= launch =======================
extern "C" void kernel_launch(void* const* d_in, const int* in_sizes, int n_in,
                              void* d_out, int out_size) {
    const float* x  = (const float*)d_in[0];   // spike_seq [25,1024,1024]
    const float* w1 = (const float*)d_in[1];   // [4096,1024]
    const float* b1 = (const float*)d_in[2];   // [4096]
    const float* w2 = (const float*)d_in[3];   // [64,4096]
    const float* b2 = (const float*)d_in[4];   // [64]
    float* out = (float*)d_out;                // [1024,64]

    __half *A, *w1hi, *w1lo, *w2hi, *w2lo, *spk1;
    float *cur1, *cur2;
    cudaGetSymbolAddress((void**)&A,    g_A);
    cudaGetSymbolAddress((void**)&w1hi, g_w1hi);
    cudaGetSymbolAddress((void**)&w1lo, g_w1lo);
    cudaGetSymbolAddress((void**)&w2hi, g_w2hi);
    cudaGetSymbolAddress((void**)&w2lo, g_w2lo);
    cudaGetSymbolAddress((void**)&spk1, g_spk1);
    cudaGetSymbolAddress((void**)&cur1, g_cur1);
    cudaGetSymbolAddress((void**)&cur2, g_cur2);

    // dynamic smem (bytes): ([2][BM][BK+8] + [2][2][BN][BK+8]) halves * 2
    constexpr int SMEM1 = (2 * 128 * 40 + 4 * 128 * 40) * 2;   // 61440 B
    constexpr int SMEM2 = (2 * 128 * 40 + 4 * 64 * 40) * 2;    // 40960 B
    cudaFuncSetAttribute((const void*)gemm_hilo<128, 128, 32, 32, 32>,
                         cudaFuncAttributeMaxDynamicSharedMemorySize, SMEM1);
    cudaFuncSetAttribute((const void*)gemm_hilo<128, 64, 32, 32, 32>,
                         cudaFuncAttributeMaxDynamicSharedMemorySize, SMEM2);

    // 1) prep: fp16 spikes + hi/scaled-lo weight splits
    k_cvt_spikes<<<4096, 256>>>(x, A, M_ROWS * IN_DIM);
    k_split<<<2048, 256>>>(w1, w1hi, w1lo, HID_DIM * IN_DIM);
    k_split<<<512, 256>>>(w2, w2hi, w2lo, OUT_DIM * HID_DIM);

    // 2) GEMM1: cur1[25600,4096] = A[25600,1024] @ w1^T + b1   (16 warps/CTA)
    gemm_hilo<128, 128, 32, 32, 32>
        <<<dim3(HID_DIM / 128, M_ROWS / 128), 512, SMEM1>>>(
            A, w1hi, w1lo, b1, cur1, M_ROWS, HID_DIM, IN_DIM);

    // 3) LIF layer 1 (sequential over t, parallel over neurons)
    lif1_kernel<<<(BATCH * HID_DIM) / 256, 256>>>(cur1, spk1);

    // 4) GEMM2: cur2[25600,64] = spk1[25600,4096] @ w2^T + b2   (8 warps/CTA)
    gemm_hilo<128, 64, 32, 32, 32>
        <<<dim3(OUT_DIM / 64, M_ROWS / 128), 256, SMEM2>>>(
            spk1, w2hi, w2lo, b2, cur2, M_ROWS, OUT_DIM, HID_DIM);

    // 5) LIF layer 2 + spike counting
    lif2_kernel<<<(BATCH * OUT_DIM) / 256, 256>>>(cur2, out);
}

// round 5
// speedup vs baseline: 1.4472x; 1.4472x over previous
#include <cuda_runtime.h>
#include <cuda_fp16.h>
#include <cstdint>
#include <cstddef>

// ======================= problem dims (fixed) =======================
#define T_STEPS 25
#define BATCH   1024
#define IN_DIM  1024
#define HID_DIM 4096
#define OUT_DIM 64
#define M_ROWS  (T_STEPS * BATCH)   // 25600

#define LO_SCALE     1024.0f
#define LO_INV_SCALE 0.0009765625f  // exact 2^-10

// ======================= static device scratch =======================
__device__ __half g_A    [(size_t)M_ROWS * IN_DIM];     // fp16 input spikes (exact 0/1)
__device__ __half g_w1hi [(size_t)HID_DIM * IN_DIM];
__device__ __half g_w1lo [(size_t)HID_DIM * IN_DIM];    // (w - hi) * 1024, fp16-normal
__device__ __half g_w2hi [(size_t)OUT_DIM * HID_DIM];
__device__ __half g_w2lo [(size_t)OUT_DIM * HID_DIM];
__device__ float  g_cur1 [(size_t)M_ROWS * HID_DIM];    // layer-1 currents
__device__ __half g_spk1 [(size_t)M_ROWS * HID_DIM];    // layer-1 spikes (exact 0/1)
__device__ float  g_cur2 [(size_t)M_ROWS * OUT_DIM];    // layer-2 currents

// ======================= helpers =======================
__device__ __forceinline__ void cp16(void* dst_smem, const void* src_gmem) {
    uint32_t d = (uint32_t)__cvta_generic_to_shared(dst_smem);
    asm volatile("cp.async.cg.shared.global [%0], [%1], 16;" :: "r"(d), "l"(src_gmem));
}
__device__ __forceinline__ void cp_commit() { asm volatile("cp.async.commit_group;"); }
__device__ __forceinline__ void cp_wait1()  { asm volatile("cp.async.wait_group 1;"); }
__device__ __forceinline__ void cp_wait0()  { asm volatile("cp.async.wait_group 0;"); }

__device__ __forceinline__ void ldsm_x4(uint32_t* r, uint32_t saddr) {
    asm volatile("ldmatrix.sync.aligned.m8n8.x4.shared.b16 {%0,%1,%2,%3}, [%4];"
        : "=r"(r[0]), "=r"(r[1]), "=r"(r[2]), "=r"(r[3]) : "r"(saddr));
}

__device__ __forceinline__ void mma16816(float* c, const uint32_t* a, uint32_t b0, uint32_t b1) {
    asm volatile(
        "mma.sync.aligned.m16n8k16.row.col.f32.f16.f16.f32 "
        "{%0,%1,%2,%3}, {%4,%5,%6,%7}, {%8,%9}, {%0,%1,%2,%3};"
        : "+f"(c[0]), "+f"(c[1]), "+f"(c[2]), "+f"(c[3])
        : "r"(a[0]), "r"(a[1]), "r"(a[2]), "r"(a[3]), "r"(b0), "r"(b1));
}

// ======================= prep kernels =======================
__global__ void k_cvt_spikes(const float* __restrict__ x, __half* __restrict__ y, int n) {
    for (int i = blockIdx.x * blockDim.x + threadIdx.x; i < n; i += gridDim.x * blockDim.x)
        y[i] = __float2half_rn(x[i]);   // 0.0 / 1.0 -> exact fp16
}

__global__ void k_split(const float* __restrict__ w, __half* __restrict__ hi,
                        __half* __restrict__ lo, int n) {
    for (int i = blockIdx.x * blockDim.x + threadIdx.x; i < n; i += gridDim.x * blockDim.x) {
        float v = w[i];
        __half h = __float2half_rn(v);
        hi[i] = h;
        // residual scaled into fp16-normal range; unscaled in the GEMM epilogue.
        // Keeping lo-plane products at this magnitude in their OWN accumulator is
        // what preserves exactness (tensor-core accum truncates tiny addends vs big C).
        lo[i] = __float2half_rn(__fmul_rn(__fsub_rn(v, __half2float(h)), LO_SCALE));
    }
}

// ====== GEMM: C[M,N] = A[M,K] @ (Whi + Wlo/1024)[N,K]^T + bias (two-plane accum) ======
// A fp16 row-major (exact 0/1), W fp16 row-major [N,K] == col-major B.
// Double-buffered cp.async; ldmatrix.x4 fragment loads; separate fp32 accumulators
// per plane, combined as acc_hi + acc_lo/1024 + bias in the epilogue.
template <int BM, int BN, int BK, int WM, int WN>
__global__ void __launch_bounds__((BM / WM) * (BN / WN) * 32, 2)
gemm_hilo(const __half* __restrict__ A,
          const __half* __restrict__ Whi,
          const __half* __restrict__ Wlo,
          const float* __restrict__ bias,
          float* __restrict__ C,
          int M, int N, int K)
{
    constexpr int BKP  = BK + 8;                 // padded k-stride (halves); BKP*2=144B, 16B-aligned rows
    constexpr int NW   = (BM / WM) * (BN / WN);
    constexpr int NTH  = NW * 32;
    constexpr int MT   = WM / 16;
    constexpr int NT   = WN / 8;                 // must be even (paired ldmatrix)
    constexpr int KCH  = BK / 8;                 // 16B chunks per row
    constexpr int ACH  = BM * KCH;
    constexpr int BCH  = BN * KCH;

    extern __shared__ __align__(16) unsigned char smem_raw[];
    __half* As = reinterpret_cast<__half*>(smem_raw);   // [2][BM][BKP]
    __half* Bs = As + 2 * BM * BKP;                      // [2][2][BN][BKP]  (stage, plane)

    const int tid  = threadIdx.x;
    const int wid  = tid >> 5;
    const int lane = tid & 31;

    const int wm0 = (wid % (BM / WM)) * WM;
    const int wn0 = (wid / (BM / WM)) * WN;
    const int bm0 = blockIdx.y * BM;
    const int bn0 = blockIdx.x * BN;
    const int NK  = K / BK;

    // ldmatrix.x4: lane L supplies the row address (L&7) of matrix (L>>3).
    const int mi = lane >> 3, rr = lane & 7;
    const int a_roff = (mi & 1) * 8 + rr;   // A matrices: (m,k),(m+8,k),(m,k+8),(m+8,k+8)
    const int a_coff = (mi >> 1) * 8;
    const int b_roff = (mi >> 1) * 8 + rr;  // B matrices: (n,k),(n,k+8),(n+8,k),(n+8,k+8)
    const int b_coff = (mi & 1) * 8;

    const uint32_t as_u = (uint32_t)__cvta_generic_to_shared(As);
    const uint32_t bs_u = (uint32_t)__cvta_generic_to_shared(Bs);

    float acc_h[MT][NT][4];
    float acc_l[MT][NT][4];
#pragma unroll
    for (int i = 0; i < MT; i++)
#pragma unroll
        for (int j = 0; j < NT; j++)
#pragma unroll
            for (int e = 0; e < 4; e++) { acc_h[i][j][e] = 0.f; acc_l[i][j][e] = 0.f; }

    auto load_stage = [&](int stage, int kt) {
        const int k0 = kt * BK;
#pragma unroll
        for (int c = tid; c < ACH; c += NTH) {
            int row = c / KCH, kc = (c % KCH) * 8;
            cp16(&As[(stage * BM + row) * BKP + kc],
                 A + (size_t)(bm0 + row) * K + k0 + kc);
        }
#pragma unroll
        for (int c = tid; c < BCH; c += NTH) {
            int row = c / KCH, kc = (c % KCH) * 8;
            size_t g = (size_t)(bn0 + row) * K + k0 + kc;
            cp16(&Bs[((stage * 2 + 0) * BN + row) * BKP + kc], Whi + g);
            cp16(&Bs[((stage * 2 + 1) * BN + row) * BKP + kc], Wlo + g);
        }
    };

    load_stage(0, 0);
    cp_commit();

    for (int kt = 0; kt < NK; kt++) {
        const int buf = kt & 1;
        if (kt + 1 < NK) {
            load_stage(buf ^ 1, kt + 1);
            cp_commit();
            cp_wait1();
        } else {
            cp_wait0();
        }
        __syncthreads();

#pragma unroll
        for (int kk = 0; kk < BK / 16; kk++) {
            uint32_t a[MT][4];
#pragma unroll
            for (int i = 0; i < MT; i++)
                ldsm_x4(a[i], as_u +
                    (uint32_t)(((buf * BM + wm0 + i * 16 + a_roff) * BKP
                                + kk * 16 + a_coff) * 2));
            // hi plane
#pragma unroll
            for (int jp = 0; jp < NT / 2; jp++) {
                uint32_t b[4];
                ldsm_x4(b, bs_u +
                    (uint32_t)((((buf * 2 + 0) * BN + wn0 + jp * 16 + b_roff) * BKP
                                + kk * 16 + b_coff) * 2));
#pragma unroll
                for (int i = 0; i < MT; i++) mma16816(acc_h[i][2 * jp],     a[i], b[0], b[1]);
#pragma unroll
                for (int i = 0; i < MT; i++) mma16816(acc_h[i][2 * jp + 1], a[i], b[2], b[3]);
            }
            // lo plane (scaled; own accumulator — no small-into-large absorption)
#pragma unroll
            for (int jp = 0; jp < NT / 2; jp++) {
                uint32_t b[4];
                ldsm_x4(b, bs_u +
                    (uint32_t)((((buf * 2 + 1) * BN + wn0 + jp * 16 + b_roff) * BKP
                                + kk * 16 + b_coff) * 2));
#pragma unroll
                for (int i = 0; i < MT; i++) mma16816(acc_l[i][2 * jp],     a[i], b[0], b[1]);
#pragma unroll
                for (int i = 0; i < MT; i++) mma16816(acc_l[i][2 * jp + 1], a[i], b[2], b[3]);
            }
        }
        __syncthreads();
    }

    // epilogue: C = acc_hi + acc_lo/1024 + bias
    const int grp = lane >> 2, q = lane & 3;
#pragma unroll
    for (int i = 0; i < MT; i++) {
#pragma unroll
        for (int j = 0; j < NT; j++) {
            int row0 = bm0 + wm0 + i * 16 + grp;
            int row1 = row0 + 8;
            int col  = bn0 + wn0 + j * 8 + q * 2;
            float bv0 = bias[col];
            float bv1 = bias[col + 1];
            float v00 = fmaf(acc_l[i][j][0], LO_INV_SCALE, acc_h[i][j][0]) + bv0;
            float v01 = fmaf(acc_l[i][j][1], LO_INV_SCALE, acc_h[i][j][1]) + bv1;
            float v10 = fmaf(acc_l[i][j][2], LO_INV_SCALE, acc_h[i][j][2]) + bv0;
            float v11 = fmaf(acc_l[i][j][3], LO_INV_SCALE, acc_h[i][j][3]) + bv1;
            *(float2*)&C[(size_t)row0 * N + col] = make_float2(v00, v01);
            *(float2*)&C[(size_t)row1 * N + col] = make_float2(v10, v11);
        }
    }
}

// ======================= LIF layer 1: currents -> spikes (fp16) =======================
// mem_t = 0.9*mem + cur_t - spk_{t-1};  spk_t = (mem_t - 1 > 0). _rn ops forbid FMA fusion.
__global__ void lif1_kernel(const float* __restrict__ cur, __half* __restrict__ spk) {
    int idx = blockIdx.x * blockDim.x + threadIdx.x;   // = b*HID + h
    if (idx >= BATCH * HID_DIM) return;
    float mem = 0.f, sp = 0.f;
#pragma unroll
    for (int t = 0; t < T_STEPS; t++) {
        float c = cur[(size_t)t * BATCH * HID_DIM + idx];
        mem = __fsub_rn(__fadd_rn(__fmul_rn(0.9f, mem), c), sp);
        sp  = (mem > 1.0f) ? 1.f : 0.f;
        spk[(size_t)t * BATCH * HID_DIM + idx] = __float2half_rn(sp);
    }
}

// ======================= LIF layer 2: currents -> spike counts =======================
__global__ void lif2_kernel(const float* __restrict__ cur, float* __restrict__ out) {
    int idx = blockIdx.x * blockDim.x + threadIdx.x;   // = b*OUT + o
    if (idx >= BATCH * OUT_DIM) return;
    float mem = 0.f, sp = 0.f, cnt = 0.f;
#pragma unroll
    for (int t = 0; t < T_STEPS; t++) {
        float c = cur[(size_t)t * BATCH * OUT_DIM + idx];
        mem = __fsub_rn(__fadd_rn(__fmul_rn(0.9f, mem), c), sp);
        sp  = (mem > 1.0f) ? 1.f : 0.f;
        cnt += sp;
    }
    out[idx] = cnt;
}

// ======================= launch =======================
extern "C" void kernel_launch(void* const* d_in, const int* in_sizes, int n_in,
                              void* d_out, int out_size) {
    const float* x  = (const float*)d_in[0];   // [25,1024,1024]
    const float* w1 = (const float*)d_in[1];   // [4096,1024]
    const float* b1 = (const float*)d_in[2];   // [4096]
    const float* w2 = (const float*)d_in[3];   // [64,4096]
    const float* b2 = (const float*)d_in[4];   // [64]
    float* out = (float*)d_out;                // [1024,64]

    __half *A, *w1hi, *w1lo, *w2hi, *w2lo, *spk1;
    float *cur1, *cur2;
    cudaGetSymbolAddress((void**)&A,    g_A);
    cudaGetSymbolAddress((void**)&w1hi, g_w1hi);
    cudaGetSymbolAddress((void**)&w1lo, g_w1lo);
    cudaGetSymbolAddress((void**)&w2hi, g_w2hi);
    cudaGetSymbolAddress((void**)&w2lo, g_w2lo);
    cudaGetSymbolAddress((void**)&spk1, g_spk1);
    cudaGetSymbolAddress((void**)&cur1, g_cur1);
    cudaGetSymbolAddress((void**)&cur2, g_cur2);

    // smem: ([2][128][72] + [2][2][64][72]) halves * 2B = 73728 B; 2 CTAs/SM fits 228KB
    constexpr int SMEM = (2 * 128 * 72 + 4 * 64 * 72) * 2;   // 73728 B
    cudaFuncSetAttribute((const void*)gemm_hilo<128, 64, 64, 32, 32>,
                         cudaFuncAttributeMaxDynamicSharedMemorySize, SMEM);

    // 1) prep
    k_cvt_spikes<<<4096, 256>>>(x, A, M_ROWS * IN_DIM);
    k_split<<<2048, 256>>>(w1, w1hi, w1lo, HID_DIM * IN_DIM);
    k_split<<<512, 256>>>(w2, w2hi, w2lo, OUT_DIM * HID_DIM);

    // 2) GEMM1: cur1[25600,4096] = A[25600,1024] @ w1^T + b1
    //    BM=128,BN=64,BK=64,WM=32,WN=32 -> 8 warps, 2 CTAs/SM, grid 64x200
    gemm_hilo<128, 64, 64, 32, 32>
        <<<dim3(HID_DIM / 64, M_ROWS / 128), 256, SMEM>>>(
            A, w1hi, w1lo, b1, cur1, M_ROWS, HID_DIM, IN_DIM);

    // 3) LIF layer 1
    lif1_kernel<<<(BATCH * HID_DIM) / 256, 256>>>(cur1, spk1);

    // 4) GEMM2: cur2[25600,64] = spk1[25600,4096] @ w2^T + b2   (same config, grid 1x200)
    gemm_hilo<128, 64, 64, 32, 32>
        <<<dim3(OUT_DIM / 64, M_ROWS / 128), 256, SMEM>>>(
            spk1, w2hi, w2lo, b2, cur2, M_ROWS, OUT_DIM, HID_DIM);

    // 5) LIF layer 2 + spike counting
    lif2_kernel<<<(BATCH * OUT_DIM) / 256, 256>>>(cur2, out);
}